// round 13
// baseline (speedup 1.0000x reference)
#include <cuda_runtime.h>
#include <math.h>

typedef unsigned long long ull;

#define BB 64
#define TT 512
#define II 256
#define HH 512
#define CC 40
#define G4 2048     // 4*H
#define NB 128      // persistent blocks, all co-resident (<=148 SMs, 1 block/SM)

// -------------------- device scratch --------------------
__device__ __align__(256) float g_xg [(size_t)BB * TT * G4];   // [m=b*T+t][n]
__device__ __align__(256) float g_xgT[(size_t)TT * G4 * BB];   // [t][n][b]
__device__ __align__(256) float g_hbuf[2 * HH * BB];           // [parity][unit][b]
__device__ volatile unsigned g_stepflag[NB * 32];              // one 128B line per block (padded — proven)

// -------------------- f32x2 helpers --------------------
__device__ __forceinline__ ull pack2(float x, float y) {
    ull r; asm("mov.b64 %0, {%1, %2};" : "=l"(r) : "f"(x), "f"(y)); return r;
}
__device__ __forceinline__ void unpack2(ull v, float& x, float& y) {
    asm("mov.b64 {%0, %1}, %2;" : "=f"(x), "=f"(y) : "l"(v));
}
__device__ __forceinline__ ull ffma2(ull a, ull b, ull c) {
    ull d; asm("fma.rn.f32x2 %0, %1, %2, %3;" : "=l"(d) : "l"(a), "l"(b), "l"(c)); return d;
}
// 32B L2 (.cg) load as four ulls
__device__ __forceinline__ void ldcg32(const void* p, ull& a, ull& b, ull& c, ull& d) {
    asm volatile("ld.global.cg.v2.u64 {%0, %1}, [%2];" : "=l"(a), "=l"(b) : "l"(p));
    asm volatile("ld.global.cg.v2.u64 {%0, %1}, [%2];" : "=l"(c), "=l"(d) : "l"((const char*)p + 16));
}

// fast activations (MUFU-based; err ~1e-6, well within 1e-3 budget)
__device__ __forceinline__ float fsig(float x) {
    return __fdividef(1.f, 1.f + __expf(-x));
}
__device__ __forceinline__ float ftanh(float x) {
    float ax = fabsf(x);
    float e  = __expf(-2.f * ax);
    float r  = __fdividef(1.f - e, 1.f + e);
    return x < 0.f ? -r : r;
}

// -------------------- kernel 1: xg = x @ W_ih^T + (b_ih + b_hh), f32x2 --------------------
__global__ void __launch_bounds__(256) gemm_xg(const float* __restrict__ x,
                                               const float* __restrict__ Wih,
                                               const float* __restrict__ bih,
                                               const float* __restrict__ bhh) {
    __shared__ __align__(16) float As[16][132];   // [k][m]
    __shared__ __align__(16) float Bs[16][132];   // [k][n] permuted
    const int tid  = threadIdx.x;
    const int m0   = blockIdx.y * 128;
    const int n0   = blockIdx.x * 128;
    const int tx   = tid & 15;
    const int ty   = tid >> 4;
    const int lrow = tid >> 2;
    const int lkq  = (tid & 3) << 2;
    char* BsB = (char*)Bs;

    ull acc2[8][4];
#pragma unroll
    for (int i = 0; i < 8; i++)
#pragma unroll
        for (int j = 0; j < 4; j++) acc2[i][j] = 0ull;

    const unsigned posA = ((unsigned)(tx & 1)) * 256u + ((unsigned)(tx >> 1)) * 16u;

    for (int k0 = 0; k0 < II; k0 += 16) {
        float4 a0 = *(const float4*)(x   + (size_t)(m0 + lrow)      * II + k0 + lkq);
        float4 a1 = *(const float4*)(x   + (size_t)(m0 + lrow + 64) * II + k0 + lkq);
        float4 b0 = *(const float4*)(Wih + (size_t)(n0 + lrow)      * II + k0 + lkq);
        float4 b1 = *(const float4*)(Wih + (size_t)(n0 + lrow + 64) * II + k0 + lkq);
        __syncthreads();
        As[lkq+0][lrow]    = a0.x; As[lkq+1][lrow]    = a0.y;
        As[lkq+2][lrow]    = a0.z; As[lkq+3][lrow]    = a0.w;
        As[lkq+0][lrow+64] = a1.x; As[lkq+1][lrow+64] = a1.y;
        As[lkq+2][lrow+64] = a1.z; As[lkq+3][lrow+64] = a1.w;
        {
            int c0 = lrow, c1 = lrow + 64;
            unsigned o0 = (unsigned)(((c0 >> 2) & 3) << 7) + (unsigned)((c0 >> 4) << 4) + (unsigned)((c0 & 3) << 2);
            unsigned o1 = (unsigned)(((c1 >> 2) & 3) << 7) + (unsigned)((c1 >> 4) << 4) + (unsigned)((c1 & 3) << 2);
            *(float*)(BsB + (lkq+0)*528 + o0) = b0.x;
            *(float*)(BsB + (lkq+1)*528 + o0) = b0.y;
            *(float*)(BsB + (lkq+2)*528 + o0) = b0.z;
            *(float*)(BsB + (lkq+3)*528 + o0) = b0.w;
            *(float*)(BsB + (lkq+0)*528 + o1) = b1.x;
            *(float*)(BsB + (lkq+1)*528 + o1) = b1.y;
            *(float*)(BsB + (lkq+2)*528 + o1) = b1.z;
            *(float*)(BsB + (lkq+3)*528 + o1) = b1.w;
        }
        __syncthreads();
#pragma unroll
        for (int k = 0; k < 16; k++) {
            float a[8];
            *(float4*)(a)     = *(float4*)&As[k][ty * 8];
            *(float4*)(a + 4) = *(float4*)&As[k][ty * 8 + 4];
            ulonglong2 bA = *(ulonglong2*)(BsB + k*528 + posA);
            ulonglong2 bB = *(ulonglong2*)(BsB + k*528 + posA + 128);
            ull b2[4] = {bA.x, bA.y, bB.x, bB.y};
#pragma unroll
            for (int i = 0; i < 8; i++) {
                ull a2 = pack2(a[i], a[i]);
                acc2[i][0] = ffma2(a2, b2[0], acc2[i][0]);
                acc2[i][1] = ffma2(a2, b2[1], acc2[i][1]);
                acc2[i][2] = ffma2(a2, b2[2], acc2[i][2]);
                acc2[i][3] = ffma2(a2, b2[3], acc2[i][3]);
            }
        }
    }

    float bias[8];
#pragma unroll
    for (int j = 0; j < 8; j++) {
        int n = n0 + tx * 8 + j;
        bias[j] = bih[n] + bhh[n];
    }
#pragma unroll
    for (int i = 0; i < 8; i++) {
        size_t m = (size_t)(m0 + ty * 8 + i);
        float o[8];
#pragma unroll
        for (int j = 0; j < 4; j++) unpack2(acc2[i][j], o[2*j], o[2*j+1]);
        float4 v0, v1;
        v0.x = o[0] + bias[0]; v0.y = o[1] + bias[1];
        v0.z = o[2] + bias[2]; v0.w = o[3] + bias[3];
        v1.x = o[4] + bias[4]; v1.y = o[5] + bias[5];
        v1.z = o[6] + bias[6]; v1.w = o[7] + bias[7];
        *(float4*)(g_xg + m * G4 + n0 + tx * 8)     = v0;
        *(float4*)(g_xg + m * G4 + n0 + tx * 8 + 4) = v1;
    }
}

// -------------------- kernel 2: transpose xg[b*T+t][n] -> xgT[t][n][b] --------------------
__global__ void __launch_bounds__(256) transpose_xg() {
    __shared__ float tile[64][65];
    const int t   = blockIdx.x;
    const int n0  = blockIdx.y << 6;
    const int tid = threadIdx.x;
    const int a   = tid & 63;
    const int r   = tid >> 6;
    for (int b = r; b < 64; b += 4)
        tile[a][b] = g_xg[(size_t)(b * TT + t) * G4 + n0 + a];
    __syncthreads();
    for (int n = r; n < 64; n += 4)
        g_xgT[((size_t)t * G4 + n0 + n) * BB + a] = tile[n][a];
}

// -------------------- noop: capture-window alignment for ncu --------------------
__global__ void noop_pad() {}

// -------------------- kernel 3: persistent LSTM recurrence --------------------
// R6 structure (zero-staging, padded flags) + incremental per-producer consumption:
//  * Block bx owns units [4bx,4bx+4) -> 16 gate rows. Warp kg owns k-split
//    [64kg,64kg+64), produced by blocks [16kg,16kg+16), 4 k-rows each.
//  * Consumer walks producers j=0..15 in order: acquire-poll producer j's padded
//    flag (all lanes read the SAME line -> one broadcast sector per poll), then
//    FMA its 4 k-rows from L2. FMA of chunk j overlaps arrival of later
//    producers, absorbing cross-SM skew; poll traffic is 1 line instead of 16.
//  * Producer publishes g_stepflag[bx] = S+1+t after writing h_t; never waits.
// smem: Wsm2 [512][16] dup-pairs 64KB | red [8][16][64] 32KB   = 96KB
#define SMEM_LSTM (65536 + 32768)
__global__ void __launch_bounds__(256, 1) lstm_rec(const float* __restrict__ Whh) {
    extern __shared__ char smc[];
    ull*   Wsm2 = (ull*)smc;                 // [512][16] {w,w}
    float* red  = (float*)(smc + 65536);     // [8][16][64]
    ull*   red2 = (ull*)red;

    const int tid = threadIdx.x;
    const int bx  = blockIdx.x;
    const unsigned S = g_stepflag[bx * 32];  // epoch base (persistent across replays)

    // Load W_hh slice: Wsm2[k*16 + lr] = dup(Whh[row(lr)][k]), lr = g*4+uu
    for (int idx = tid; idx < 16 * 512; idx += 256) {
        int k   = idx >> 4;
        int lr  = idx & 15;
        int row = ((lr >> 2) << 9) + (bx << 2) + (lr & 3);
        float w = Whh[(size_t)row * HH + k];
        Wsm2[(k << 4) + lr] = pack2(w, w);
    }

    // elementwise-role mapping
    const int b  = tid & 63;
    const int uu = tid >> 6;
    const int ug = (bx << 2) + uu;

    g_hbuf[ug * 64 + b] = 0.f;    // h0 = 0 (parity 0)
    float c = 0.f;
    __syncthreads();
    if (tid == 0) { __threadfence(); g_stepflag[bx * 32] = S + 1; }  // h_0 ready

    // compute-role mapping
    const int kg   = tid >> 5;      // warp id = k-split, krange 64
    const int lane = tid & 31;
    const int rq   = lane >> 3;     // rows 4rq..4rq+3
    const int bq   = lane & 7;      // batches 8bq..8bq+7
    const ull* wk0 = Wsm2 + ((kg << 6) << 4) + (rq << 2);
    const int rb = (kg << 9) + (rq << 2) * 32 + (bq << 2);  // red2 ull base
    const int krow0 = kg << 6;

    for (int t = 0; t < TT; t++) {
        const int p = t & 1;

        // prefetch xg for this step (independent of h)
        float xgv[4];
#pragma unroll
        for (int g = 0; g < 4; g++)
            xgv[g] = __ldg(&g_xgT[((size_t)t * G4 + (g << 9) + ug) * 64 + b]);

        const unsigned want = S + 1 + (unsigned)t;

        ull acc[4][4];
#pragma unroll
        for (int j = 0; j < 4; j++)
#pragma unroll
            for (int u = 0; u < 4; u++) acc[j][u] = 0ull;

        const char* hk = (const char*)(g_hbuf + (size_t)p * HH * 64)
                       + (krow0 << 8) + (bq << 5);       // k*256B + bq*32B
        const ull* wk = wk0;

        // walk this warp's 16 producers in order; FMA each one's 4 k-rows on arrival
        for (int j = 0; j < 16; j++) {
            const unsigned* fj = (const unsigned*)&g_stepflag[((kg << 4) + j) * 32];
            unsigned fv;
            do {
                asm volatile("ld.acquire.gpu.global.u32 %0, [%1];" : "=r"(fv) : "l"(fj));
            } while ((int)(fv - want) < 0);

#pragma unroll
            for (int k = 0; k < 4; k++) {
                ull hx, hy, hz, hw;
                ldcg32(hk, hx, hy, hz, hw);                       // 8 batches of h[k]
                ulonglong2 wa = *(const ulonglong2*)(wk);         // rows 4rq,4rq+1 (dup)
                ulonglong2 wb = *(const ulonglong2*)(wk + 2);     // rows 4rq+2,4rq+3
                hk += 256; wk += 16;
                acc[0][0] = ffma2(wa.x, hx, acc[0][0]);
                acc[0][1] = ffma2(wa.x, hy, acc[0][1]);
                acc[0][2] = ffma2(wa.x, hz, acc[0][2]);
                acc[0][3] = ffma2(wa.x, hw, acc[0][3]);
                acc[1][0] = ffma2(wa.y, hx, acc[1][0]);
                acc[1][1] = ffma2(wa.y, hy, acc[1][1]);
                acc[1][2] = ffma2(wa.y, hz, acc[1][2]);
                acc[1][3] = ffma2(wa.y, hw, acc[1][3]);
                acc[2][0] = ffma2(wb.x, hx, acc[2][0]);
                acc[2][1] = ffma2(wb.x, hy, acc[2][1]);
                acc[2][2] = ffma2(wb.x, hz, acc[2][2]);
                acc[2][3] = ffma2(wb.x, hw, acc[2][3]);
                acc[3][0] = ffma2(wb.y, hx, acc[3][0]);
                acc[3][1] = ffma2(wb.y, hy, acc[3][1]);
                acc[3][2] = ffma2(wb.y, hz, acc[3][2]);
                acc[3][3] = ffma2(wb.y, hw, acc[3][3]);
            }
        }

#pragma unroll
        for (int j = 0; j < 4; j++) {
            *(ulonglong2*)(red2 + rb + j * 32)     = make_ulonglong2(acc[j][0], acc[j][1]);
            *(ulonglong2*)(red2 + rb + j * 32 + 2) = make_ulonglong2(acc[j][2], acc[j][3]);
        }
        __syncthreads();

        // elementwise: combine 8 split-k partials + xg, gates, state update
        float s[4];
#pragma unroll
        for (int g = 0; g < 4; g++) {
            int lr = (g << 2) + uu;
            float v = 0.f;
#pragma unroll
            for (int k2 = 0; k2 < 8; k2++)
                v += red[(k2 << 10) + lr * 64 + b];
            s[g] = v + xgv[g];
        }
        float ig = fsig(s[0]);
        float fg = fsig(s[1]);
        float gg = ftanh(s[2]);
        float og = fsig(s[3]);
        c = fmaf(fg, c, ig * gg);
        float h = og * ftanh(c);
        g_hbuf[((p ^ 1) * HH + ug) * 64 + b] = h;
        __syncthreads();   // all h writes of this block done
        if (tid == 0) { __threadfence(); g_stepflag[bx * 32] = S + 2 + (unsigned)t; }
    }
    // h_last = h_512 in parity 0
}

// -------------------- kernel 4: out = h_last @ W_fc^T + b_fc --------------------
__global__ void __launch_bounds__(256) fc_out(const float* __restrict__ Wfc,
                                              const float* __restrict__ bfc,
                                              float* __restrict__ out) {
    __shared__ float hs[HH];
    const int b = blockIdx.x;
    for (int u = threadIdx.x; u < HH; u += 256) hs[u] = g_hbuf[u * 64 + b];
    __syncthreads();
    const int w = threadIdx.x >> 5, lane = threadIdx.x & 31;
    for (int cc = w; cc < CC; cc += 8) {
        float s = 0.f;
        for (int u = lane; u < HH; u += 32) s = fmaf(hs[u], Wfc[cc * HH + u], s);
#pragma unroll
        for (int o = 16; o; o >>= 1) s += __shfl_xor_sync(0xffffffffu, s, o);
        if (lane == 0) out[b * CC + cc] = s + bfc[cc];
    }
}

// -------------------- launch --------------------
extern "C" void kernel_launch(void* const* d_in, const int* in_sizes, int n_in,
                              void* d_out, int out_size) {
    (void)in_sizes; (void)n_in; (void)out_size;
    const float* x   = (const float*)d_in[0];
    const float* Wih = (const float*)d_in[1];
    const float* Whh = (const float*)d_in[2];
    const float* bih = (const float*)d_in[3];
    const float* bhh = (const float*)d_in[4];
    const float* Wfc = (const float*)d_in[5];
    const float* bfc = (const float*)d_in[6];
    float* out = (float*)d_out;

    gemm_xg<<<dim3(G4 / 128, (BB * TT) / 128), 256>>>(x, Wih, bih, bhh);
    transpose_xg<<<dim3(TT, G4 / 64), 256>>>();
    noop_pad<<<1, 32>>>();   // aligns ncu capture index onto lstm_rec

    cudaFuncSetAttribute(lstm_rec, cudaFuncAttributeMaxDynamicSharedMemorySize, SMEM_LSTM);
    lstm_rec<<<NB, 256, SMEM_LSTM>>>(Whh);

    fc_out<<<BB, 256>>>(Wfc, bfc, out);
}

// round 14
// speedup vs baseline: 1.5447x; 1.5447x over previous
#include <cuda_runtime.h>
#include <math.h>

typedef unsigned long long ull;

#define BB 64
#define TT 512
#define II 256
#define HH 512
#define CC 40
#define G4 2048     // 4*H
#define NB 128      // persistent blocks, all co-resident (<=148 SMs, 1 block/SM)

// -------------------- device scratch --------------------
__device__ __align__(256) float g_xg [(size_t)BB * TT * G4];   // [m=b*T+t][n]
__device__ __align__(256) float g_xgT[(size_t)TT * G4 * BB];   // [t][n][b]
__device__ __align__(256) float g_hbuf[2 * HH * BB];           // [parity][unit][b]
__device__ volatile unsigned g_stepflag[NB * 32];              // one 128B line per block (padded — proven)

// -------------------- f32x2 helpers --------------------
__device__ __forceinline__ ull pack2(float x, float y) {
    ull r; asm("mov.b64 %0, {%1, %2};" : "=l"(r) : "f"(x), "f"(y)); return r;
}
__device__ __forceinline__ void unpack2(ull v, float& x, float& y) {
    asm("mov.b64 {%0, %1}, %2;" : "=f"(x), "=f"(y) : "l"(v));
}
__device__ __forceinline__ ull ffma2(ull a, ull b, ull c) {
    ull d; asm("fma.rn.f32x2 %0, %1, %2, %3;" : "=l"(d) : "l"(a), "l"(b), "l"(c)); return d;
}
// 32B L2 (.cg) load as four ulls
__device__ __forceinline__ void ldcg32(const void* p, ull& a, ull& b, ull& c, ull& d) {
    asm volatile("ld.global.cg.v2.u64 {%0, %1}, [%2];" : "=l"(a), "=l"(b) : "l"(p));
    asm volatile("ld.global.cg.v2.u64 {%0, %1}, [%2];" : "=l"(c), "=l"(d) : "l"((const char*)p + 16));
}

// fast activations (MUFU-based; err ~1e-6, well within 1e-3 budget)
__device__ __forceinline__ float fsig(float x) {
    return __fdividef(1.f, 1.f + __expf(-x));
}
__device__ __forceinline__ float ftanh(float x) {
    float ax = fabsf(x);
    float e  = __expf(-2.f * ax);
    float r  = __fdividef(1.f - e, 1.f + e);
    return x < 0.f ? -r : r;
}

// -------------------- kernel 1: xg = x @ W_ih^T + (b_ih + b_hh), f32x2 --------------------
__global__ void __launch_bounds__(256) gemm_xg(const float* __restrict__ x,
                                               const float* __restrict__ Wih,
                                               const float* __restrict__ bih,
                                               const float* __restrict__ bhh) {
    __shared__ __align__(16) float As[16][132];   // [k][m]
    __shared__ __align__(16) float Bs[16][132];   // [k][n] permuted
    const int tid  = threadIdx.x;
    const int m0   = blockIdx.y * 128;
    const int n0   = blockIdx.x * 128;
    const int tx   = tid & 15;
    const int ty   = tid >> 4;
    const int lrow = tid >> 2;
    const int lkq  = (tid & 3) << 2;
    char* BsB = (char*)Bs;

    ull acc2[8][4];
#pragma unroll
    for (int i = 0; i < 8; i++)
#pragma unroll
        for (int j = 0; j < 4; j++) acc2[i][j] = 0ull;

    const unsigned posA = ((unsigned)(tx & 1)) * 256u + ((unsigned)(tx >> 1)) * 16u;

    for (int k0 = 0; k0 < II; k0 += 16) {
        float4 a0 = *(const float4*)(x   + (size_t)(m0 + lrow)      * II + k0 + lkq);
        float4 a1 = *(const float4*)(x   + (size_t)(m0 + lrow + 64) * II + k0 + lkq);
        float4 b0 = *(const float4*)(Wih + (size_t)(n0 + lrow)      * II + k0 + lkq);
        float4 b1 = *(const float4*)(Wih + (size_t)(n0 + lrow + 64) * II + k0 + lkq);
        __syncthreads();
        As[lkq+0][lrow]    = a0.x; As[lkq+1][lrow]    = a0.y;
        As[lkq+2][lrow]    = a0.z; As[lkq+3][lrow]    = a0.w;
        As[lkq+0][lrow+64] = a1.x; As[lkq+1][lrow+64] = a1.y;
        As[lkq+2][lrow+64] = a1.z; As[lkq+3][lrow+64] = a1.w;
        {
            int c0 = lrow, c1 = lrow + 64;
            unsigned o0 = (unsigned)(((c0 >> 2) & 3) << 7) + (unsigned)((c0 >> 4) << 4) + (unsigned)((c0 & 3) << 2);
            unsigned o1 = (unsigned)(((c1 >> 2) & 3) << 7) + (unsigned)((c1 >> 4) << 4) + (unsigned)((c1 & 3) << 2);
            *(float*)(BsB + (lkq+0)*528 + o0) = b0.x;
            *(float*)(BsB + (lkq+1)*528 + o0) = b0.y;
            *(float*)(BsB + (lkq+2)*528 + o0) = b0.z;
            *(float*)(BsB + (lkq+3)*528 + o0) = b0.w;
            *(float*)(BsB + (lkq+0)*528 + o1) = b1.x;
            *(float*)(BsB + (lkq+1)*528 + o1) = b1.y;
            *(float*)(BsB + (lkq+2)*528 + o1) = b1.z;
            *(float*)(BsB + (lkq+3)*528 + o1) = b1.w;
        }
        __syncthreads();
#pragma unroll
        for (int k = 0; k < 16; k++) {
            float a[8];
            *(float4*)(a)     = *(float4*)&As[k][ty * 8];
            *(float4*)(a + 4) = *(float4*)&As[k][ty * 8 + 4];
            ulonglong2 bA = *(ulonglong2*)(BsB + k*528 + posA);
            ulonglong2 bB = *(ulonglong2*)(BsB + k*528 + posA + 128);
            ull b2[4] = {bA.x, bA.y, bB.x, bB.y};
#pragma unroll
            for (int i = 0; i < 8; i++) {
                ull a2 = pack2(a[i], a[i]);
                acc2[i][0] = ffma2(a2, b2[0], acc2[i][0]);
                acc2[i][1] = ffma2(a2, b2[1], acc2[i][1]);
                acc2[i][2] = ffma2(a2, b2[2], acc2[i][2]);
                acc2[i][3] = ffma2(a2, b2[3], acc2[i][3]);
            }
        }
    }

    float bias[8];
#pragma unroll
    for (int j = 0; j < 8; j++) {
        int n = n0 + tx * 8 + j;
        bias[j] = bih[n] + bhh[n];
    }
#pragma unroll
    for (int i = 0; i < 8; i++) {
        size_t m = (size_t)(m0 + ty * 8 + i);
        float o[8];
#pragma unroll
        for (int j = 0; j < 4; j++) unpack2(acc2[i][j], o[2*j], o[2*j+1]);
        float4 v0, v1;
        v0.x = o[0] + bias[0]; v0.y = o[1] + bias[1];
        v0.z = o[2] + bias[2]; v0.w = o[3] + bias[3];
        v1.x = o[4] + bias[4]; v1.y = o[5] + bias[5];
        v1.z = o[6] + bias[6]; v1.w = o[7] + bias[7];
        *(float4*)(g_xg + m * G4 + n0 + tx * 8)     = v0;
        *(float4*)(g_xg + m * G4 + n0 + tx * 8 + 4) = v1;
    }
}

// -------------------- kernel 2: transpose xg[b*T+t][n] -> xgT[t][n][b] --------------------
__global__ void __launch_bounds__(256) transpose_xg() {
    __shared__ float tile[64][65];
    const int t   = blockIdx.x;
    const int n0  = blockIdx.y << 6;
    const int tid = threadIdx.x;
    const int a   = tid & 63;
    const int r   = tid >> 6;
    for (int b = r; b < 64; b += 4)
        tile[a][b] = g_xg[(size_t)(b * TT + t) * G4 + n0 + a];
    __syncthreads();
    for (int n = r; n < 64; n += 4)
        g_xgT[((size_t)t * G4 + n0 + n) * BB + a] = tile[n][a];
}

// -------------------- noop: capture-window alignment for ncu --------------------
__global__ void noop_pad() {}

// -------------------- kernel 3: persistent LSTM recurrence --------------------
// R6 structure (zero-staging, padded flags, PARALLEL poll) with 512 threads:
//  * Block bx owns units [4bx,4bx+4) -> 16 gate rows. 16 warps; warp kg owns
//    k-split [32kg,32kg+32), produced by blocks [8kg,8kg+8). Warp polls all its
//    8 producers' padded flags in ONE instruction (lanes 0..7), then reads its
//    8KB h slice directly from L2 (ld.global.cg) inside the FMA loop.
//  * 2x warps vs R6 -> 25% occ, halved per-warp loop depth, doubled LSU
//    parallelism: hides the L2 latency the profile showed as the stall source.
//  * Producer publishes g_stepflag[bx] = S+1+t after writing h_t; never waits.
// smem: Wsm2 [512][16] dup-pairs 64KB | red [16][16][64] 64KB   = 128KB
#define SMEM_LSTM (65536 + 65536)
__global__ void __launch_bounds__(512, 1) lstm_rec(const float* __restrict__ Whh) {
    extern __shared__ char smc[];
    ull*   Wsm2 = (ull*)smc;                 // [512][16] {w,w}
    float* red  = (float*)(smc + 65536);     // [16][16][64]
    ull*   red2 = (ull*)red;

    const int tid = threadIdx.x;
    const int bx  = blockIdx.x;
    const unsigned S = g_stepflag[bx * 32];  // epoch base (persistent across replays)

    // Load W_hh slice: Wsm2[k*16 + lr] = dup(Whh[row(lr)][k]), lr = g*4+uu
    for (int idx = tid; idx < 16 * 512; idx += 512) {
        int k   = idx >> 4;
        int lr  = idx & 15;
        int row = ((lr >> 2) << 9) + (bx << 2) + (lr & 3);
        float w = Whh[(size_t)row * HH + k];
        Wsm2[(k << 4) + lr] = pack2(w, w);
    }

    // elementwise-role mapping (threads 0..255 only)
    const int b  = tid & 63;
    const int uu = (tid >> 6) & 3;
    const int ug = (bx << 2) + uu;

    if (tid < 256) g_hbuf[ug * 64 + b] = 0.f;   // h0 = 0 (parity 0)
    float c = 0.f;
    __syncthreads();
    if (tid == 0) { __threadfence(); g_stepflag[bx * 32] = S + 1; }  // h_0 ready

    // compute-role mapping
    const int kg   = tid >> 5;      // warp id 0..15 = k-split, krange 32
    const int lane = tid & 31;
    const int rq   = lane >> 3;     // rows 4rq..4rq+3
    const int bq   = lane & 7;      // batches 8bq..8bq+7
    const int prod = ((kg << 3) + (lane & 7)) * 32;    // producer flag index (padded)
    const ull* wk0 = Wsm2 + ((kg << 5) << 4) + (rq << 2);
    const int rb = (kg << 9) + (rq << 2) * 32 + (bq << 2);  // red2 ull base
    const int krow0 = kg << 5;      // warp's first k row

    for (int t = 0; t < TT; t++) {
        const int p = t & 1;

        // prefetch xg for this step (independent of h; threads 0..255)
        float xgv[4];
        if (tid < 256) {
#pragma unroll
            for (int g = 0; g < 4; g++)
                xgv[g] = __ldg(&g_xgT[((size_t)t * G4 + (g << 9) + ug) * 64 + b]);
        }

        // wait for this warp's 8 producers (parallel poll, one instr per retry)
        {
            const unsigned want = S + 1 + (unsigned)t;
            while ((int)(g_stepflag[prod] - want) < 0) { }
            __syncwarp();
            __threadfence();   // acquire: order h reads after flag observation
        }

        ull acc[4][4];
#pragma unroll
        for (int j = 0; j < 4; j++)
#pragma unroll
            for (int u = 0; u < 4; u++) acc[j][u] = 0ull;

        const char* hk = (const char*)(g_hbuf + (size_t)p * HH * 64)
                       + (krow0 << 8) + (bq << 5);       // k*256B + bq*32B
        const ull* wk = wk0;
#pragma unroll 8
        for (int k = 0; k < 32; k++) {
            ull hx, hy, hz, hw;
            ldcg32(hk, hx, hy, hz, hw);                       // 8 batches of h[k]
            ulonglong2 wa = *(const ulonglong2*)(wk);         // rows 4rq,4rq+1 (dup)
            ulonglong2 wb = *(const ulonglong2*)(wk + 2);     // rows 4rq+2,4rq+3
            hk += 256; wk += 16;
            acc[0][0] = ffma2(wa.x, hx, acc[0][0]);
            acc[0][1] = ffma2(wa.x, hy, acc[0][1]);
            acc[0][2] = ffma2(wa.x, hz, acc[0][2]);
            acc[0][3] = ffma2(wa.x, hw, acc[0][3]);
            acc[1][0] = ffma2(wa.y, hx, acc[1][0]);
            acc[1][1] = ffma2(wa.y, hy, acc[1][1]);
            acc[1][2] = ffma2(wa.y, hz, acc[1][2]);
            acc[1][3] = ffma2(wa.y, hw, acc[1][3]);
            acc[2][0] = ffma2(wb.x, hx, acc[2][0]);
            acc[2][1] = ffma2(wb.x, hy, acc[2][1]);
            acc[2][2] = ffma2(wb.x, hz, acc[2][2]);
            acc[2][3] = ffma2(wb.x, hw, acc[2][3]);
            acc[3][0] = ffma2(wb.y, hx, acc[3][0]);
            acc[3][1] = ffma2(wb.y, hy, acc[3][1]);
            acc[3][2] = ffma2(wb.y, hz, acc[3][2]);
            acc[3][3] = ffma2(wb.y, hw, acc[3][3]);
        }

#pragma unroll
        for (int j = 0; j < 4; j++) {
            *(ulonglong2*)(red2 + rb + j * 32)     = make_ulonglong2(acc[j][0], acc[j][1]);
            *(ulonglong2*)(red2 + rb + j * 32 + 2) = make_ulonglong2(acc[j][2], acc[j][3]);
        }
        __syncthreads();

        // elementwise: combine 16 split-k partials + xg, gates, state update
        if (tid < 256) {
            float s[4];
#pragma unroll
            for (int g = 0; g < 4; g++) {
                int lr = (g << 2) + uu;
                float v = 0.f;
#pragma unroll
                for (int k2 = 0; k2 < 16; k2++)
                    v += red[(k2 << 10) + lr * 64 + b];
                s[g] = v + xgv[g];
            }
            float ig = fsig(s[0]);
            float fg = fsig(s[1]);
            float gg = ftanh(s[2]);
            float og = fsig(s[3]);
            c = fmaf(fg, c, ig * gg);
            float h = og * ftanh(c);
            g_hbuf[((p ^ 1) * HH + ug) * 64 + b] = h;
        }
        __syncthreads();   // all h writes of this block done
        if (tid == 0) { __threadfence(); g_stepflag[bx * 32] = S + 2 + (unsigned)t; }
    }
    // h_last = h_512 in parity 0
}

// -------------------- kernel 4: out = h_last @ W_fc^T + b_fc --------------------
__global__ void __launch_bounds__(256) fc_out(const float* __restrict__ Wfc,
                                              const float* __restrict__ bfc,
                                              float* __restrict__ out) {
    __shared__ float hs[HH];
    const int b = blockIdx.x;
    for (int u = threadIdx.x; u < HH; u += 256) hs[u] = g_hbuf[u * 64 + b];
    __syncthreads();
    const int w = threadIdx.x >> 5, lane = threadIdx.x & 31;
    for (int cc = w; cc < CC; cc += 8) {
        float s = 0.f;
        for (int u = lane; u < HH; u += 32) s = fmaf(hs[u], Wfc[cc * HH + u], s);
#pragma unroll
        for (int o = 16; o; o >>= 1) s += __shfl_xor_sync(0xffffffffu, s, o);
        if (lane == 0) out[b * CC + cc] = s + bfc[cc];
    }
}

// -------------------- launch --------------------
extern "C" void kernel_launch(void* const* d_in, const int* in_sizes, int n_in,
                              void* d_out, int out_size) {
    (void)in_sizes; (void)n_in; (void)out_size;
    const float* x   = (const float*)d_in[0];
    const float* Wih = (const float*)d_in[1];
    const float* Whh = (const float*)d_in[2];
    const float* bih = (const float*)d_in[3];
    const float* bhh = (const float*)d_in[4];
    const float* Wfc = (const float*)d_in[5];
    const float* bfc = (const float*)d_in[6];
    float* out = (float*)d_out;

    gemm_xg<<<dim3(G4 / 128, (BB * TT) / 128), 256>>>(x, Wih, bih, bhh);
    transpose_xg<<<dim3(TT, G4 / 64), 256>>>();
    noop_pad<<<1, 32>>>();   // aligns ncu capture index onto lstm_rec

    cudaFuncSetAttribute(lstm_rec, cudaFuncAttributeMaxDynamicSharedMemorySize, SMEM_LSTM);
    lstm_rec<<<NB, 512, SMEM_LSTM>>>(Whh);

    fc_out<<<BB, 256>>>(Wfc, bfc, out);
}

// round 15
// speedup vs baseline: 1.9482x; 1.2612x over previous
#include <cuda_runtime.h>
#include <math.h>

typedef unsigned long long ull;

#define BB 64
#define TT 512
#define II 256
#define HH 512
#define CC 40
#define G4 2048     // 4*H
#define NB 128      // persistent blocks, all co-resident (<=148 SMs, 1 block/SM)

// -------------------- device scratch --------------------
__device__ __align__(256) float g_xg [(size_t)BB * TT * G4];   // [m=b*T+t][n]
__device__ __align__(256) float g_xgT[(size_t)TT * G4 * BB];   // [t][n][b]
__device__ __align__(256) float g_hbuf[2 * HH * BB];           // [parity][unit][b]
__device__ volatile unsigned g_stepflag[NB * 32];              // one 128B line per block (padded — proven)

// -------------------- f32x2 helpers --------------------
__device__ __forceinline__ ull pack2(float x, float y) {
    ull r; asm("mov.b64 %0, {%1, %2};" : "=l"(r) : "f"(x), "f"(y)); return r;
}
__device__ __forceinline__ void unpack2(ull v, float& x, float& y) {
    asm("mov.b64 {%0, %1}, %2;" : "=f"(x), "=f"(y) : "l"(v));
}
__device__ __forceinline__ ull ffma2(ull a, ull b, ull c) {
    ull d; asm("fma.rn.f32x2 %0, %1, %2, %3;" : "=l"(d) : "l"(a), "l"(b), "l"(c)); return d;
}
// 32B L2 (.cg) load as four ulls
__device__ __forceinline__ void ldcg32(const void* p, ull& a, ull& b, ull& c, ull& d) {
    asm volatile("ld.global.cg.v2.u64 {%0, %1}, [%2];" : "=l"(a), "=l"(b) : "l"(p));
    asm volatile("ld.global.cg.v2.u64 {%0, %1}, [%2];" : "=l"(c), "=l"(d) : "l"((const char*)p + 16));
}

// fast activations (MUFU-based; err ~1e-6, well within 1e-3 budget)
__device__ __forceinline__ float fsig(float x) {
    return __fdividef(1.f, 1.f + __expf(-x));
}
__device__ __forceinline__ float ftanh(float x) {
    float ax = fabsf(x);
    float e  = __expf(-2.f * ax);
    float r  = __fdividef(1.f - e, 1.f + e);
    return x < 0.f ? -r : r;
}

// -------------------- kernel 1: xg = x @ W_ih^T + (b_ih + b_hh), f32x2 --------------------
__global__ void __launch_bounds__(256) gemm_xg(const float* __restrict__ x,
                                               const float* __restrict__ Wih,
                                               const float* __restrict__ bih,
                                               const float* __restrict__ bhh) {
    __shared__ __align__(16) float As[16][132];   // [k][m]
    __shared__ __align__(16) float Bs[16][132];   // [k][n] permuted
    const int tid  = threadIdx.x;
    const int m0   = blockIdx.y * 128;
    const int n0   = blockIdx.x * 128;
    const int tx   = tid & 15;
    const int ty   = tid >> 4;
    const int lrow = tid >> 2;
    const int lkq  = (tid & 3) << 2;
    char* BsB = (char*)Bs;

    ull acc2[8][4];
#pragma unroll
    for (int i = 0; i < 8; i++)
#pragma unroll
        for (int j = 0; j < 4; j++) acc2[i][j] = 0ull;

    const unsigned posA = ((unsigned)(tx & 1)) * 256u + ((unsigned)(tx >> 1)) * 16u;

    for (int k0 = 0; k0 < II; k0 += 16) {
        float4 a0 = *(const float4*)(x   + (size_t)(m0 + lrow)      * II + k0 + lkq);
        float4 a1 = *(const float4*)(x   + (size_t)(m0 + lrow + 64) * II + k0 + lkq);
        float4 b0 = *(const float4*)(Wih + (size_t)(n0 + lrow)      * II + k0 + lkq);
        float4 b1 = *(const float4*)(Wih + (size_t)(n0 + lrow + 64) * II + k0 + lkq);
        __syncthreads();
        As[lkq+0][lrow]    = a0.x; As[lkq+1][lrow]    = a0.y;
        As[lkq+2][lrow]    = a0.z; As[lkq+3][lrow]    = a0.w;
        As[lkq+0][lrow+64] = a1.x; As[lkq+1][lrow+64] = a1.y;
        As[lkq+2][lrow+64] = a1.z; As[lkq+3][lrow+64] = a1.w;
        {
            int c0 = lrow, c1 = lrow + 64;
            unsigned o0 = (unsigned)(((c0 >> 2) & 3) << 7) + (unsigned)((c0 >> 4) << 4) + (unsigned)((c0 & 3) << 2);
            unsigned o1 = (unsigned)(((c1 >> 2) & 3) << 7) + (unsigned)((c1 >> 4) << 4) + (unsigned)((c1 & 3) << 2);
            *(float*)(BsB + (lkq+0)*528 + o0) = b0.x;
            *(float*)(BsB + (lkq+1)*528 + o0) = b0.y;
            *(float*)(BsB + (lkq+2)*528 + o0) = b0.z;
            *(float*)(BsB + (lkq+3)*528 + o0) = b0.w;
            *(float*)(BsB + (lkq+0)*528 + o1) = b1.x;
            *(float*)(BsB + (lkq+1)*528 + o1) = b1.y;
            *(float*)(BsB + (lkq+2)*528 + o1) = b1.z;
            *(float*)(BsB + (lkq+3)*528 + o1) = b1.w;
        }
        __syncthreads();
#pragma unroll
        for (int k = 0; k < 16; k++) {
            float a[8];
            *(float4*)(a)     = *(float4*)&As[k][ty * 8];
            *(float4*)(a + 4) = *(float4*)&As[k][ty * 8 + 4];
            ulonglong2 bA = *(ulonglong2*)(BsB + k*528 + posA);
            ulonglong2 bB = *(ulonglong2*)(BsB + k*528 + posA + 128);
            ull b2[4] = {bA.x, bA.y, bB.x, bB.y};
#pragma unroll
            for (int i = 0; i < 8; i++) {
                ull a2 = pack2(a[i], a[i]);
                acc2[i][0] = ffma2(a2, b2[0], acc2[i][0]);
                acc2[i][1] = ffma2(a2, b2[1], acc2[i][1]);
                acc2[i][2] = ffma2(a2, b2[2], acc2[i][2]);
                acc2[i][3] = ffma2(a2, b2[3], acc2[i][3]);
            }
        }
    }

    float bias[8];
#pragma unroll
    for (int j = 0; j < 8; j++) {
        int n = n0 + tx * 8 + j;
        bias[j] = bih[n] + bhh[n];
    }
#pragma unroll
    for (int i = 0; i < 8; i++) {
        size_t m = (size_t)(m0 + ty * 8 + i);
        float o[8];
#pragma unroll
        for (int j = 0; j < 4; j++) unpack2(acc2[i][j], o[2*j], o[2*j+1]);
        float4 v0, v1;
        v0.x = o[0] + bias[0]; v0.y = o[1] + bias[1];
        v0.z = o[2] + bias[2]; v0.w = o[3] + bias[3];
        v1.x = o[4] + bias[4]; v1.y = o[5] + bias[5];
        v1.z = o[6] + bias[6]; v1.w = o[7] + bias[7];
        *(float4*)(g_xg + m * G4 + n0 + tx * 8)     = v0;
        *(float4*)(g_xg + m * G4 + n0 + tx * 8 + 4) = v1;
    }
}

// -------------------- kernel 2: transpose xg[b*T+t][n] -> xgT[t][n][b] --------------------
__global__ void __launch_bounds__(256) transpose_xg() {
    __shared__ float tile[64][65];
    const int t   = blockIdx.x;
    const int n0  = blockIdx.y << 6;
    const int tid = threadIdx.x;
    const int a   = tid & 63;
    const int r   = tid >> 6;
    for (int b = r; b < 64; b += 4)
        tile[a][b] = g_xg[(size_t)(b * TT + t) * G4 + n0 + a];
    __syncthreads();
    for (int n = r; n < 64; n += 4)
        g_xgT[((size_t)t * G4 + n0 + n) * BB + a] = tile[n][a];
}

// -------------------- noop: capture-window alignment for ncu --------------------
__global__ void noop_pad() {}

// -------------------- kernel 3: persistent LSTM recurrence --------------------
// Batch-split tiling (512 threads, proven sync):
//  * Block bx = (ublk, bh): 8 units (32 gate rows) x 32 batches (half).
//    Chip h traffic halves: each SM reads h[512][32] = 64KB/step.
//  * 16 warps; warp kg owns k-split [32kg,32kg+32), produced by the 4 blocks
//    (ublk' in [4kg,4kg+4), same bh). Parallel tight-spin poll on 4 padded flags.
//  * Inner iter: 2 LDG.128 (one 128B line) + 1 LDS.128 (w float, 8x16B
//    conflict-free) + 4 dup-movs (ALU) + 16 FFMA2 -> 3 mem instr per 16 FMA.
//  * Producer publishes g_stepflag[bx] = S+1+t after writing its h slice.
// smem: Wsm float [512][32] 64KB | red [16][32][32] 64KB = 128KB
#define SMEM_LSTM (65536 + 65536)
__global__ void __launch_bounds__(512, 1) lstm_rec(const float* __restrict__ Whh) {
    extern __shared__ char smc[];
    float* Wsm  = (float*)smc;               // [512][32]  w[k][lr]
    float* red  = (float*)(smc + 65536);     // [16][32][32]
    ull*   red2 = (ull*)red;

    const int tid  = threadIdx.x;
    const int bx   = blockIdx.x;
    const int ublk = bx >> 1;                // unit group (8 units)
    const int bh   = bx & 1;                 // batch half
    const unsigned S = g_stepflag[bx * 32];  // epoch base (persistent across replays)

    // Load W_hh slice: Wsm[k*32 + lr] = Whh[row(lr)][k], lr = g*8+u
    for (int idx = tid; idx < 32 * 512; idx += 512) {
        int k   = idx >> 5;
        int lr  = idx & 31;
        int row = ((lr >> 3) << 9) + (ublk << 3) + (lr & 7);
        Wsm[(k << 5) + lr] = Whh[(size_t)row * HH + k];
    }

    // elementwise-role mapping (threads 0..255): cell (u, b32)
    const int uu  = tid >> 5;        // 0..7  (unit within group; valid for tid<256)
    const int b32 = tid & 31;        // batch within half
    const int ug  = (ublk << 3) + uu;

    if (tid < 256) g_hbuf[ug * 64 + (bh << 5) + b32] = 0.f;   // h0 = 0 (parity 0)
    float c = 0.f;
    __syncthreads();
    if (tid == 0) { __threadfence(); g_stepflag[bx * 32] = S + 1; }  // h_0 ready

    // compute-role mapping
    const int kg   = tid >> 5;      // warp id 0..15 = k-split, krange 32
    const int lane = tid & 31;
    const int rq   = lane >> 2;     // 0..7 -> rows 4rq..4rq+3 (of 32 local rows)
    const int bq   = lane & 3;      // 0..3 -> batches 8bq..8bq+7 (of 32)
    // producers: blocks (4kg + i)*2 + bh, i = lane&3
    const int prod = ((((kg << 2) + (lane & 3)) << 1) + bh) * 32;
    const float* wk0 = Wsm + (kg << 5 << 5) + (rq << 2);     // k=32kg, rows 4rq..
    const int rb = (kg << 9) + (rq << 6) + (bq << 2);        // red2 ull base; row j adds 16
    const int krow0 = kg << 5;

    for (int t = 0; t < TT; t++) {
        const int p = t & 1;

        // prefetch xg for this step (independent of h; threads 0..255)
        float xgv[4];
        if (tid < 256) {
#pragma unroll
            for (int g = 0; g < 4; g++)
                xgv[g] = __ldg(&g_xgT[((size_t)t * G4 + (g << 9) + ug) * 64 + (bh << 5) + b32]);
        }

        // wait for this warp's 4 producers (parallel poll, one instr per retry)
        {
            const unsigned want = S + 1 + (unsigned)t;
            while ((int)(g_stepflag[prod] - want) < 0) { }
            __syncwarp();
            __threadfence();   // acquire: order h reads after flag observation
        }

        ull acc[4][4];
#pragma unroll
        for (int j = 0; j < 4; j++)
#pragma unroll
            for (int u = 0; u < 4; u++) acc[j][u] = 0ull;

        const char* hk = (const char*)(g_hbuf + (size_t)p * HH * 64)
                       + (krow0 << 8) + (bh << 7) + (bq << 5);   // k*256B + half*128B + bq*32B
        const float* wk = wk0;
#pragma unroll 4
        for (int k = 0; k < 32; k++) {
            ull hx, hy, hz, hw;
            ldcg32(hk, hx, hy, hz, hw);                  // 8 batches of h[k] (this half)
            float4 wv = *(const float4*)wk;              // rows 4rq..4rq+3 at this k
            hk += 256; wk += 32;
            ull w0 = pack2(wv.x, wv.x);
            ull w1 = pack2(wv.y, wv.y);
            ull w2 = pack2(wv.z, wv.z);
            ull w3 = pack2(wv.w, wv.w);
            acc[0][0] = ffma2(w0, hx, acc[0][0]);
            acc[0][1] = ffma2(w0, hy, acc[0][1]);
            acc[0][2] = ffma2(w0, hz, acc[0][2]);
            acc[0][3] = ffma2(w0, hw, acc[0][3]);
            acc[1][0] = ffma2(w1, hx, acc[1][0]);
            acc[1][1] = ffma2(w1, hy, acc[1][1]);
            acc[1][2] = ffma2(w1, hz, acc[1][2]);
            acc[1][3] = ffma2(w1, hw, acc[1][3]);
            acc[2][0] = ffma2(w2, hx, acc[2][0]);
            acc[2][1] = ffma2(w2, hy, acc[2][1]);
            acc[2][2] = ffma2(w2, hz, acc[2][2]);
            acc[2][3] = ffma2(w2, hw, acc[2][3]);
            acc[3][0] = ffma2(w3, hx, acc[3][0]);
            acc[3][1] = ffma2(w3, hy, acc[3][1]);
            acc[3][2] = ffma2(w3, hz, acc[3][2]);
            acc[3][3] = ffma2(w3, hw, acc[3][3]);
        }

        // red[kg][lr][b32]: partials for rows 4rq..4rq+3, batches 8bq..8bq+7
#pragma unroll
        for (int j = 0; j < 4; j++) {
            *(ulonglong2*)(red2 + rb + j * 16)     = make_ulonglong2(acc[j][0], acc[j][1]);
            *(ulonglong2*)(red2 + rb + j * 16 + 2) = make_ulonglong2(acc[j][2], acc[j][3]);
        }
        __syncthreads();

        // elementwise: combine 16 split-k partials + xg, gates, state update
        if (tid < 256) {
            float s[4];
#pragma unroll
            for (int g = 0; g < 4; g++) {
                int lr = (g << 3) + uu;
                float v = 0.f;
#pragma unroll
                for (int k2 = 0; k2 < 16; k2++)
                    v += red[(k2 << 10) + (lr << 5) + b32];
                s[g] = v + xgv[g];
            }
            float ig = fsig(s[0]);
            float fg = fsig(s[1]);
            float gg = ftanh(s[2]);
            float og = fsig(s[3]);
            c = fmaf(fg, c, ig * gg);
            float h = og * ftanh(c);
            g_hbuf[((p ^ 1) * HH + ug) * 64 + (bh << 5) + b32] = h;
        }
        __syncthreads();   // all h writes of this block done
        if (tid == 0) { __threadfence(); g_stepflag[bx * 32] = S + 2 + (unsigned)t; }
    }
    // h_last = h_512 in parity 0
}

// -------------------- kernel 4: out = h_last @ W_fc^T + b_fc --------------------
__global__ void __launch_bounds__(256) fc_out(const float* __restrict__ Wfc,
                                              const float* __restrict__ bfc,
                                              float* __restrict__ out) {
    __shared__ float hs[HH];
    const int b = blockIdx.x;
    for (int u = threadIdx.x; u < HH; u += 256) hs[u] = g_hbuf[u * 64 + b];
    __syncthreads();
    const int w = threadIdx.x >> 5, lane = threadIdx.x & 31;
    for (int cc = w; cc < CC; cc += 8) {
        float s = 0.f;
        for (int u = lane; u < HH; u += 32) s = fmaf(hs[u], Wfc[cc * HH + u], s);
#pragma unroll
        for (int o = 16; o; o >>= 1) s += __shfl_xor_sync(0xffffffffu, s, o);
        if (lane == 0) out[b * CC + cc] = s + bfc[cc];
    }
}

// -------------------- launch --------------------
extern "C" void kernel_launch(void* const* d_in, const int* in_sizes, int n_in,
                              void* d_out, int out_size) {
    (void)in_sizes; (void)n_in; (void)out_size;
    const float* x   = (const float*)d_in[0];
    const float* Wih = (const float*)d_in[1];
    const float* Whh = (const float*)d_in[2];
    const float* bih = (const float*)d_in[3];
    const float* bhh = (const float*)d_in[4];
    const float* Wfc = (const float*)d_in[5];
    const float* bfc = (const float*)d_in[6];
    float* out = (float*)d_out;

    gemm_xg<<<dim3(G4 / 128, (BB * TT) / 128), 256>>>(x, Wih, bih, bhh);
    transpose_xg<<<dim3(TT, G4 / 64), 256>>>();
    noop_pad<<<1, 32>>>();   // aligns ncu capture index onto lstm_rec

    cudaFuncSetAttribute(lstm_rec, cudaFuncAttributeMaxDynamicSharedMemorySize, SMEM_LSTM);
    lstm_rec<<<NB, 512, SMEM_LSTM>>>(Whh);

    fc_out<<<BB, 256>>>(Wfc, bfc, out);
}